// round 16
// baseline (speedup 1.0000x reference)
#include <cuda_runtime.h>
#include <cuda_fp16.h>
#include <cstdint>

// ---------------------------------------------------------------------------
// Problem constants
// ---------------------------------------------------------------------------
#define BATCH 8
#define CH    512
#define CP    256                     // channel pairs
#define LEN   8192
#define PADL  8
#define LPAD  (LEN + 2*PADL)          // 8208
#define KTOT  1536                    // 3 taps * 512 ch (single fp16)
#define WELEM (512*512*3)             // 786432 elems per weight tensor

// conv tiling (R11/R15 winner): BM=128, BN=256, 16 warps, warp 64m x 32n
#define BM 128
#define BN 256
#define NCHUNK 24
#define NSTG 2
#define ASTR 72                       // A smem row stride (fp16): 64 + 8 pad
#define BCOLS 272                     // B cols per row: [-8, 264) u32 (halo)
#define BSTR 296                      // B smem row stride (u32): ==8 mod 32
#define A_BYTES (128 * ASTR * 2)      // 18432
#define B_BYTES (32 * BSTR * 4)       // 37888
#define STAGE_BYTES (A_BYTES + B_BYTES)          // 56320
#define SMEM_TOTAL (NSTG * STAGE_BYTES)          // 112640
#define NB16 (32 * (BCOLS / 4))       // cp.async.16 per B tile: 2176

// ---------------------------------------------------------------------------
// Scratch (device globals — no allocation allowed)
// Activations: u32 = {fp16 ch(2cp), fp16 ch(2cp+1)} indexed [b*CP+cp][pos]
// ---------------------------------------------------------------------------
__device__ uint32_t g_X2[(size_t)BATCH*CP*LPAD];
__device__ uint32_t g_H2[(size_t)BATCH*CP*LPAD];
__device__ __half   g_Wq[(size_t)6*512*KTOT];   // ternary weights [o][k=tap*512+c]
__device__ float    g_scales[6];
__device__ float    g_partial[6*64];

// ---------------------------------------------------------------------------
// Helpers
// ---------------------------------------------------------------------------
__device__ __forceinline__ uint32_t smem_u32(const void* p) {
    return (uint32_t)__cvta_generic_to_shared(p);
}
__device__ __forceinline__ uint32_t pack2h(float a, float b) {
    return (uint32_t)__half_as_ushort(__float2half_rn(a)) |
           ((uint32_t)__half_as_ushort(__float2half_rn(b)) << 16);
}
__device__ __forceinline__ void cp16(uint32_t dst, const void* src) {
    asm volatile("cp.async.cg.shared.global [%0], [%1], 16;\n" :: "r"(dst), "l"(src));
}
__device__ __forceinline__ void ldmA(uint32_t a[4], uint32_t addr) {
    asm volatile("ldmatrix.sync.aligned.m8n8.x4.shared.b16 {%0,%1,%2,%3}, [%4];\n"
                 : "=r"(a[0]), "=r"(a[1]), "=r"(a[2]), "=r"(a[3]) : "r"(addr));
}
__device__ __forceinline__ void mma16816(float c[4], const uint32_t a[4], const uint32_t b[2]) {
    asm volatile(
        "mma.sync.aligned.m16n8k16.row.col.f32.f16.f16.f32 "
        "{%0,%1,%2,%3}, {%4,%5,%6,%7}, {%8,%9}, {%0,%1,%2,%3};\n"
        : "+f"(c[0]), "+f"(c[1]), "+f"(c[2]), "+f"(c[3])
        : "r"(a[0]), "r"(a[1]), "r"(a[2]), "r"(a[3]), "r"(b[0]), "r"(b[1]));
}
// fp16-accumulate HMMA: D,C are 2x fp16x2 regs
__device__ __forceinline__ void mma16816h(uint32_t d[2], const uint32_t a[4],
                                          const uint32_t b[2],
                                          uint32_t c0, uint32_t c1) {
    asm volatile(
        "mma.sync.aligned.m16n8k16.row.col.f16.f16.f16.f16 "
        "{%0,%1}, {%2,%3,%4,%5}, {%6,%7}, {%8,%9};\n"
        : "=r"(d[0]), "=r"(d[1])
        : "r"(a[0]), "r"(a[1]), "r"(a[2]), "r"(a[3]),
          "r"(b[0]), "r"(b[1]), "r"(c0), "r"(c1));
}

// ---------------------------------------------------------------------------
// Weight prep: absmean scale, two-phase (64x6 partial blocks -> full-chip BW)
// ---------------------------------------------------------------------------
__global__ void scales_part_kernel(const float* w0, const float* w1, const float* w2,
                                   const float* w3, const float* w4, const float* w5) {
    const float* ws[6] = {w0, w1, w2, w3, w4, w5};
    const float* w = ws[blockIdx.y];
    __shared__ float red[256];
    const int chunk = WELEM / 64;                 // 12288
    int base = blockIdx.x * chunk;
    float s = 0.f;
    for (int i = threadIdx.x; i < chunk; i += 256) s += fabsf(w[base + i]);
    red[threadIdx.x] = s;
    __syncthreads();
    for (int o = 128; o; o >>= 1) {
        if (threadIdx.x < o) red[threadIdx.x] += red[threadIdx.x + o];
        __syncthreads();
    }
    if (threadIdx.x == 0) g_partial[blockIdx.y * 64 + blockIdx.x] = red[0];
}

// quant + folded final scale reduction (widx is constant per block: WELEM%256==0)
__global__ void quant_kernel(const float* w0, const float* w1, const float* w2,
                             const float* w3, const float* w4, const float* w5) {
    const float* ws[6] = {w0, w1, w2, w3, w4, w5};
    size_t idx = (size_t)blockIdx.x * 256 + threadIdx.x;
    int widx = (int)(idx / WELEM);
    __shared__ float sScale;
    if (threadIdx.x == 0) {
        float t = 0.f;
        for (int j = 0; j < 64; ++j) t += g_partial[widx * 64 + j];
        float sc = t / (float)WELEM + 1e-5f;
        sScale = sc;
        if (blockIdx.x % 3072 == 0) g_scales[widx] = sc;   // one writer per widx
    }
    __syncthreads();
    if (idx >= (size_t)6 * WELEM) return;
    int rem  = (int)(idx % WELEM);
    int o    = rem / 1536;
    int r2   = rem % 1536;
    int tap  = r2 / 512;
    int cc   = r2 % 512;
    float v = ws[widx][((size_t)o * 512 + cc) * 3 + tap];
    float q = rintf(v / sScale);                  // round-half-even, matches jnp.round
    q = fminf(1.f, fmaxf(-1.f, q));
    g_Wq[(size_t)widx * 512 * KTOT + (size_t)o * KTOT + tap * 512 + cc] = __float2half_rn(q);
}

// ---------------------------------------------------------------------------
// Split (once, branch 0): fp32 [c][pos] -> fp16x2 u32 [cp][pos] + copy x->out.
// Zeroes halo regions (epilogues write interior only, so they stay 0).
// grid: (ceil(LPAD/256), BATCH*CP)
// ---------------------------------------------------------------------------
__global__ void split_kernel(const float* __restrict__ src, float* __restrict__ cpy) {
    int p  = blockIdx.x * 256 + threadIdx.x;
    int b  = blockIdx.y >> 8;
    int cp = blockIdx.y & 255;
    size_t row = (size_t)b * CP + cp;
    if (blockIdx.x == 0 && threadIdx.x < 16) {
        int j = threadIdx.x;                      // halo: 0..7 and 8200..8207
        g_H2[row * LPAD + (j < 8 ? j : LEN + j)] = 0u;
    }
    if (p >= LPAD) return;
    int l = p - PADL;
    float v0 = 0.f, v1 = 0.f;
    bool in = (l >= 0) && (l < LEN);
    size_t s0 = ((size_t)(b * CH + 2 * cp)) * LEN + l;
    if (in) {
        v0 = src[s0];
        v1 = src[s0 + LEN];
    }
    g_X2[row * LPAD + p] = pack2h(v0, v1);
    if (in) {
        cpy[s0] = v0;
        cpy[s0 + LEN] = v1;
    }
}

// ---------------------------------------------------------------------------
// convA: fp16-ACCUM HMMA probe.  Reads g_X2; per-chunk fp16 accumulation
// (partial sums small) flushed into fp32 accumulators each chunk.
// Epilogue scale+bias+leaky -> fp16 pairs into g_H2.
// grid: (LEN/BN, CH/BM, BATCH), block 512, dynamic smem SMEM_TOTAL
// ---------------------------------------------------------------------------
__global__ __launch_bounds__(512, 1)
void convA_kernel(const float* __restrict__ bias, int widx, int dil) {
    extern __shared__ char smem[];

    const int lBase = blockIdx.x * BN;
    const int oBase = blockIdx.y * BM;
    const int bIdx  = blockIdx.z;
    const int tid   = threadIdx.x;
    const int lane  = tid & 31;
    const int wid   = tid >> 5;
    const int wm    = wid >> 3;
    const int wn    = wid & 7;
    const int g     = lane >> 2;
    const int tq    = lane & 3;

    const __half* Aw = g_Wq + (size_t)widx * 512 * KTOT;

    uint32_t  aB[NSTG];
    uint32_t  bB[NSTG];
    const uint32_t* bP[NSTG];
#pragma unroll
    for (int s = 0; s < NSTG; ++s) {
        char* stg = smem + s * STAGE_BYTES;
        aB[s] = smem_u32(stg);
        bB[s] = smem_u32(stg + A_BYTES);
        bP[s] = (const uint32_t*)(stg + A_BYTES);
    }

    float c[4][4][4];
#pragma unroll
    for (int mi = 0; mi < 4; ++mi)
#pragma unroll
        for (int ni = 0; ni < 4; ++ni)
#pragma unroll
            for (int r = 0; r < 4; ++r) c[mi][ni][r] = 0.f;

    auto loadStage = [&](int st, int kc) {
        {
            int q = tid * 2;
#pragma unroll
            for (int u = 0; u < 2; ++u, ++q) {
                int m   = q >> 3;
                int kch = q & 7;
                cp16(aB[st] + (uint32_t)(m * ASTR + kch * 8) * 2,
                     Aw + (size_t)(oBase + m) * KTOT + kc * 64 + kch * 8);
            }
        }
        {
            int cB = (kc & 7) << 5;
            const uint32_t* srcBase =
                g_X2 + ((size_t)(bIdx * CP + cB)) * LPAD + (PADL + lBase - 8);
#pragma unroll
            for (int j = 0; j < 5; ++j) {
                int r = tid + 512 * j;
                if (r < NB16) {
                    int p = r / (BCOLS / 4);
                    int q = r % (BCOLS / 4);
                    cp16(bB[st] + (uint32_t)(p * BSTR + q * 4) * 4,
                         srcBase + (size_t)p * LPAD + q * 4);
                }
            }
        }
    };

    auto mmaStage = [&](int st, int colOfs) {
        const uint32_t* Bsl = bP[st];
        uint32_t ch[4][4][2];                     // fp16x2 chunk accumulators
#pragma unroll
        for (int s = 0; s < 4; ++s) {
            uint32_t afr[4][4];
#pragma unroll
            for (int mi = 0; mi < 4; ++mi) {
                uint32_t addr = aB[st] +
                    (uint32_t)(((wm * 64 + mi * 16 + (lane & 15)) * ASTR) +
                               s * 16 + ((lane >> 4) << 3)) * 2;
                ldmA(afr[mi], addr);
            }
            uint32_t bfr[4][2];
#pragma unroll
            for (int ni = 0; ni < 4; ++ni) {
                int col = colOfs + wn * 32 + ni * 8 + g;
                bfr[ni][0] = Bsl[(s * 8 + tq) * BSTR + col];
                bfr[ni][1] = Bsl[(s * 8 + 4 + tq) * BSTR + col];
            }
#pragma unroll
            for (int mi = 0; mi < 4; ++mi)
#pragma unroll
                for (int ni = 0; ni < 4; ++ni) {
                    if (s == 0)
                        mma16816h(ch[mi][ni], afr[mi], bfr[ni], 0u, 0u);
                    else
                        mma16816h(ch[mi][ni], afr[mi], bfr[ni],
                                  ch[mi][ni][0], ch[mi][ni][1]);
                }
        }
        // flush chunk partials into fp32
#pragma unroll
        for (int mi = 0; mi < 4; ++mi)
#pragma unroll
            for (int ni = 0; ni < 4; ++ni) {
                float2 f0 = __half22float2(*reinterpret_cast<__half2*>(&ch[mi][ni][0]));
                float2 f1 = __half22float2(*reinterpret_cast<__half2*>(&ch[mi][ni][1]));
                c[mi][ni][0] += f0.x;
                c[mi][ni][1] += f0.y;
                c[mi][ni][2] += f1.x;
                c[mi][ni][3] += f1.y;
            }
    };

    loadStage(0, 0);
    asm volatile("cp.async.commit_group;\n" ::: "memory");

    for (int kc = 0; kc < NCHUNK; ++kc) {
        asm volatile("cp.async.wait_group 0;\n" ::: "memory");
        __syncthreads();
        if (kc + 1 < NCHUNK) {
            loadStage((kc + 1) & 1, kc + 1);
            asm volatile("cp.async.commit_group;\n" ::: "memory");
        }
        int tap = kc >> 3;
        mmaStage(kc & 1, 8 + (tap - 1) * dil);
    }

    // ---- epilogue: scale+bias+leaky -> fp16 pairs into g_H2
    const float scale = g_scales[widx];
#pragma unroll
    for (int mi = 0; mi < 4; ++mi) {
        int o0 = oBase + wm * 64 + mi * 16 + g;
        float bv0 = bias[o0];
        float bv1 = bias[o0 + 8];
#pragma unroll
        for (int ni = 0; ni < 4; ++ni) {
            int l = lBase + wn * 32 + ni * 8 + tq * 2;
            float v0 = c[mi][ni][0] * scale + bv0;
            float v1 = c[mi][ni][1] * scale + bv0;
            float v2 = c[mi][ni][2] * scale + bv1;
            float v3 = c[mi][ni][3] * scale + bv1;
            v0 = (v0 >= 0.f) ? v0 : 0.1f * v0;
            v1 = (v1 >= 0.f) ? v1 : 0.1f * v1;
            v2 = (v2 >= 0.f) ? v2 : 0.1f * v2;
            v3 = (v3 >= 0.f) ? v3 : 0.1f * v3;
            float p0 = __shfl_xor_sync(0xffffffffu, v0, 4);
            float p1 = __shfl_xor_sync(0xffffffffu, v1, 4);
            float p2 = __shfl_xor_sync(0xffffffffu, v2, 4);
            float p3 = __shfl_xor_sync(0xffffffffu, v3, 4);
            if ((g & 1) == 0) {
                int cp0 = o0 >> 1;
                int cp1 = cp0 + 4;
                size_t r0i = ((size_t)(bIdx * CP + cp0)) * LPAD + PADL + l;
                size_t r1i = ((size_t)(bIdx * CP + cp1)) * LPAD + PADL + l;
                *(uint2*)(&g_H2[r0i]) = make_uint2(pack2h(v0, p0), pack2h(v1, p1));
                *(uint2*)(&g_H2[r1i]) = make_uint2(pack2h(v2, p2), pack2h(v3, p3));
            }
        }
    }
}

// ---------------------------------------------------------------------------
// convB: fp32-accum HMMA (R15, unchanged).  Reads g_H2; epilogue residual
// -> fp32 out; if writeNext, packs out_new into g_X2 for the next branch.
// ---------------------------------------------------------------------------
__global__ __launch_bounds__(512, 1)
void convB_kernel(const float* __restrict__ bias, int widx,
                  float* __restrict__ outF, int writeNext) {
    extern __shared__ char smem[];

    const int lBase = blockIdx.x * BN;
    const int oBase = blockIdx.y * BM;
    const int bIdx  = blockIdx.z;
    const int tid   = threadIdx.x;
    const int lane  = tid & 31;
    const int wid   = tid >> 5;
    const int wm    = wid >> 3;
    const int wn    = wid & 7;
    const int g     = lane >> 2;
    const int tq    = lane & 3;

    const __half* Aw = g_Wq + (size_t)widx * 512 * KTOT;

    uint32_t  aB[NSTG];
    uint32_t  bB[NSTG];
    const uint32_t* bP[NSTG];
#pragma unroll
    for (int s = 0; s < NSTG; ++s) {
        char* stg = smem + s * STAGE_BYTES;
        aB[s] = smem_u32(stg);
        bB[s] = smem_u32(stg + A_BYTES);
        bP[s] = (const uint32_t*)(stg + A_BYTES);
    }

    float c[4][4][4];
#pragma unroll
    for (int mi = 0; mi < 4; ++mi)
#pragma unroll
        for (int ni = 0; ni < 4; ++ni)
#pragma unroll
            for (int r = 0; r < 4; ++r) c[mi][ni][r] = 0.f;

    auto loadStage = [&](int st, int kc) {
        {
            int q = tid * 2;
#pragma unroll
            for (int u = 0; u < 2; ++u, ++q) {
                int m   = q >> 3;
                int kch = q & 7;
                cp16(aB[st] + (uint32_t)(m * ASTR + kch * 8) * 2,
                     Aw + (size_t)(oBase + m) * KTOT + kc * 64 + kch * 8);
            }
        }
        {
            int cB = (kc & 7) << 5;
            const uint32_t* srcBase =
                g_H2 + ((size_t)(bIdx * CP + cB)) * LPAD + (PADL + lBase - 8);
#pragma unroll
            for (int j = 0; j < 5; ++j) {
                int r = tid + 512 * j;
                if (r < NB16) {
                    int p = r / (BCOLS / 4);
                    int q = r % (BCOLS / 4);
                    cp16(bB[st] + (uint32_t)(p * BSTR + q * 4) * 4,
                         srcBase + (size_t)p * LPAD + q * 4);
                }
            }
        }
    };

    auto mmaStage = [&](int st, int colOfs) {
        const uint32_t* Bsl = bP[st];
#pragma unroll
        for (int s = 0; s < 4; ++s) {
            uint32_t afr[4][4];
#pragma unroll
            for (int mi = 0; mi < 4; ++mi) {
                uint32_t addr = aB[st] +
                    (uint32_t)(((wm * 64 + mi * 16 + (lane & 15)) * ASTR) +
                               s * 16 + ((lane >> 4) << 3)) * 2;
                ldmA(afr[mi], addr);
            }
            uint32_t bfr[4][2];
#pragma unroll
            for (int ni = 0; ni < 4; ++ni) {
                int col = colOfs + wn * 32 + ni * 8 + g;
                bfr[ni][0] = Bsl[(s * 8 + tq) * BSTR + col];
                bfr[ni][1] = Bsl[(s * 8 + 4 + tq) * BSTR + col];
            }
#pragma unroll
            for (int mi = 0; mi < 4; ++mi)
#pragma unroll
                for (int ni = 0; ni < 4; ++ni)
                    mma16816(c[mi][ni], afr[mi], bfr[ni]);
        }
    };

    loadStage(0, 0);
    asm volatile("cp.async.commit_group;\n" ::: "memory");

    for (int kc = 0; kc < NCHUNK; ++kc) {
        asm volatile("cp.async.wait_group 0;\n" ::: "memory");
        __syncthreads();
        if (kc + 1 < NCHUNK) {
            loadStage((kc + 1) & 1, kc + 1);
            asm volatile("cp.async.commit_group;\n" ::: "memory");
        }
        int tap = kc >> 3;
        mmaStage(kc & 1, 8 + (tap - 1));          // dense conv: dil = 1
    }

    const float scale = g_scales[widx];
#pragma unroll
    for (int mi = 0; mi < 4; ++mi) {
        int o0 = oBase + wm * 64 + mi * 16 + g;
        float bv0 = bias[o0];
        float bv1 = bias[o0 + 8];
#pragma unroll
        for (int ni = 0; ni < 4; ++ni) {
            int l = lBase + wn * 32 + ni * 8 + tq * 2;
            float v0 = c[mi][ni][0] * scale + bv0;
            float v1 = c[mi][ni][1] * scale + bv0;
            float v2 = c[mi][ni][2] * scale + bv1;
            float v3 = c[mi][ni][3] * scale + bv1;
            size_t i0 = ((size_t)(bIdx * CH + o0)) * LEN + l;
            size_t i1 = ((size_t)(bIdx * CH + o0 + 8)) * LEN + l;
            float2 r0 = *(const float2*)(outF + i0);
            float2 r1 = *(const float2*)(outF + i1);
            float n0 = v0 + r0.x, n1 = v1 + r0.y;
            float n2 = v2 + r1.x, n3 = v3 + r1.y;
            *(float2*)(outF + i0) = make_float2(n0, n1);
            *(float2*)(outF + i1) = make_float2(n2, n3);
            if (writeNext) {
                float p0 = __shfl_xor_sync(0xffffffffu, n0, 4);
                float p1 = __shfl_xor_sync(0xffffffffu, n1, 4);
                float p2 = __shfl_xor_sync(0xffffffffu, n2, 4);
                float p3 = __shfl_xor_sync(0xffffffffu, n3, 4);
                if ((g & 1) == 0) {
                    int cp0 = o0 >> 1;
                    int cp1 = cp0 + 4;
                    size_t r0i = ((size_t)(bIdx * CP + cp0)) * LPAD + PADL + l;
                    size_t r1i = ((size_t)(bIdx * CP + cp1)) * LPAD + PADL + l;
                    *(uint2*)(&g_X2[r0i]) = make_uint2(pack2h(n0, p0), pack2h(n1, p1));
                    *(uint2*)(&g_X2[r1i]) = make_uint2(pack2h(n2, p2), pack2h(n3, p3));
                }
            }
        }
    }
}

// ---------------------------------------------------------------------------
// Launch.  ncu's fixed profiled slot is launch index 3 -> convA(branch0).
//   0: scales_part  1: quant  2: split  3: convA br0  4: convB br0 ...
// ---------------------------------------------------------------------------
extern "C" void kernel_launch(void* const* d_in, const int* in_sizes, int n_in,
                              void* d_out, int out_size) {
    const float* x = (const float*)d_in[0];
    const float* W[6];
    const float* Bv[6];
    for (int i = 0; i < 6; ++i) {
        W[i]  = (const float*)d_in[1 + 2 * i];
        Bv[i] = (const float*)d_in[2 + 2 * i];
    }
    float* out = (float*)d_out;

    cudaFuncSetAttribute(convA_kernel,
                         cudaFuncAttributeMaxDynamicSharedMemorySize, SMEM_TOTAL);
    cudaFuncSetAttribute(convB_kernel,
                         cudaFuncAttributeMaxDynamicSharedMemorySize, SMEM_TOTAL);

    scales_part_kernel<<<dim3(64, 6), 256>>>(W[0], W[1], W[2], W[3], W[4], W[5]);
    {
        size_t total = (size_t)6 * WELEM;
        int blocks = (int)((total + 255) / 256);
        quant_kernel<<<blocks, 256>>>(W[0], W[1], W[2], W[3], W[4], W[5]);
    }

    const dim3 cgrid(LEN / BN, CH / BM, BATCH);
    const dim3 sgrid((LPAD + 255) / 256, BATCH * CP);
    const int dils[3] = {1, 3, 5};

    split_kernel<<<sgrid, 256>>>(x, out);

    for (int br = 0; br < 3; ++br) {
        convA_kernel<<<cgrid, 512, SMEM_TOTAL>>>(Bv[2 * br], 2 * br, dils[br]);
        convB_kernel<<<cgrid, 512, SMEM_TOTAL>>>(Bv[2 * br + 1], 2 * br + 1,
                                                 out, br < 2 ? 1 : 0);
    }
}